// round 16
// baseline (speedup 1.0000x reference)
#include <cuda_runtime.h>
#include <cstdint>

// NodeDropout: out[e] = values[e] unless src or dst node dropped.
// Key measured law: throughput ∝ warps/SM (1.9% DRAM per warp), capped by
// smem. R15: shrink smem bitmask to 112,640B (nodes < 901,120) so TWO
// 768-thread CTAs fit per SM -> 48 warps (was 32). Overflow nodes (~9.9%
// of lookups) read the global bitmask (12KB slice, L2-resident, predicated).

#define MAX_BIT_WORDS 65536   // full bitmask in global (up to 2M nodes)
#define SPLIT_NODES  901120   // nodes below this use the smem bitmask
#define SPLIT_WORDS  (SPLIT_NODES / 32)   // 28,160 words = 112,640 B

__device__ unsigned int g_bits[MAX_BIT_WORDS];

// ---- pre-kernel: pack flags (4-byte 0/nonzero) into bitmask via ballot ----
__global__ void pack_flags_kernel(const unsigned int* __restrict__ flags,
                                  int N, int nwords)
{
    int t = blockIdx.x * blockDim.x + threadIdx.x;
    int w = t >> 5;
    int lane = t & 31;
    if (w >= nwords) return;
    int idx = w * 32 + lane;
    unsigned int f = (idx < N) ? flags[idx] : 0u;
    unsigned int ballot = __ballot_sync(0xFFFFFFFFu, f != 0u);
    if (lane == 0) g_bits[w] = ballot;
}

// bit lookup: smem for nodes < SPLIT_NODES, global (L2) for the rest
__device__ __forceinline__ unsigned int bit2(const unsigned int* __restrict__ sbits,
                                             int i)
{
    unsigned int w;
    if (i < SPLIT_NODES) w = sbits[i >> 5];
    else                 w = g_bits[i >> 5];
    return (w >> (i & 31)) & 1u;
}

// ---- main kernel: TWO CTAs/SM, split bitmask, 4 edges/thread/iter ----
__global__ void __launch_bounds__(768, 2)
node_dropout_kernel(const int* __restrict__ ei,
                    const float* __restrict__ vals,
                    float* __restrict__ out,
                    int E)
{
    extern __shared__ unsigned int bits[];
    for (int i = threadIdx.x; i < SPLIT_WORDS; i += blockDim.x)
        bits[i] = g_bits[i];
    __syncthreads();

    int nvec = E >> 2;  // groups of 4 edges
    int stride = gridDim.x * blockDim.x;
    for (int g = blockIdx.x * blockDim.x + threadIdx.x; g < nvec; g += stride) {
        int base = g * 4;
        int4   s = __ldcs(reinterpret_cast<const int4*>(ei + base));      // src
        int4   d = __ldcs(reinterpret_cast<const int4*>(ei + E + base));  // dst
        float4 v = __ldcs(reinterpret_cast<const float4*>(vals + base));

        float4 r;
        r.x = (bit2(bits, s.x) | bit2(bits, d.x)) ? 0.0f : v.x;
        r.y = (bit2(bits, s.y) | bit2(bits, d.y)) ? 0.0f : v.y;
        r.z = (bit2(bits, s.z) | bit2(bits, d.z)) ? 0.0f : v.z;
        r.w = (bit2(bits, s.w) | bit2(bits, d.w)) ? 0.0f : v.w;

        __stcs(reinterpret_cast<float4*>(out + base), r);
    }

    // scalar tail (E % 4 edges), block 0 thread 0
    if (blockIdx.x == 0 && threadIdx.x == 0) {
        for (int e = nvec * 4; e < E; ++e) {
            int s = ei[e];
            int d = ei[E + e];
            out[e] = (bit2(bits, s) | bit2(bits, d)) ? 0.0f : vals[e];
        }
    }
}

extern "C" void kernel_launch(void* const* d_in, const int* in_sizes, int n_in,
                              void* d_out, int out_size)
{
    const int*          ei    = (const int*)d_in[0];          // [2, E] int32
    const float*        vals  = (const float*)d_in[1];        // [E] float32
    const unsigned int* flags = (const unsigned int*)d_in[2]; // [N] 4-byte 0/nonzero
    float* out = (float*)d_out;

    int E = in_sizes[1];
    int N = in_sizes[2];
    int nwords = (N + 31) / 32;

    int num_sms = 0;
    cudaDeviceGetAttribute(&num_sms, cudaDevAttrMultiProcessorCount, 0);
    if (num_sms <= 0) num_sms = 148;

    size_t smem_bytes = (size_t)SPLIT_WORDS * sizeof(unsigned int);  // 112,640 B
    cudaFuncSetAttribute(node_dropout_kernel,
                         cudaFuncAttributeMaxDynamicSharedMemorySize,
                         (int)smem_bytes);

    // 1) pack flags -> full bitmask in global
    {
        int total_threads = nwords * 32;
        int threads = 256;
        int blocks = (total_threads + threads - 1) / threads;
        pack_flags_kernel<<<blocks, threads>>>(flags, N, nwords);
    }

    // 2) masked copy, two CTAs per SM (48 warps/SM)
    node_dropout_kernel<<<2 * num_sms, 768, smem_bytes>>>(ei, vals, out, E);
}